// round 15
// baseline (speedup 1.0000x reference)
#include <cuda_runtime.h>
#include <cuda_bf16.h>
#include <cuda_fp16.h>
#include <cstdint>

typedef __nv_bfloat16 bf16;

#define BB  2
#define SS  1024
#define HH  1024
#define NHH 16
#define HDD 64
#define WW  4
#define LL  5120   /* (W+1)*S */

// ---------------- scratch (device globals) ----------------
__device__ bf16     g_kv[(size_t)BB*LL*HH];
__device__ bf16     g_wq[HH*HH], g_wk[HH*HH], g_wv[HH*HH], g_wo[HH*HH];  // bf16 [k][n]
__device__ __half   g_qh[(size_t)BB*NHH*SS*HDD];
__device__ __half   g_kh[(size_t)BB*NHH*LL*HDD];
__device__ __half   g_vh[(size_t)BB*NHH*LL*HDD];
__device__ bf16     g_ctx[(size_t)BB*SS*HH];
__device__ float    g_rope[SS][2*32];

// ---------------- helpers ----------------
__device__ __forceinline__ void mma16816(float* d, const uint32_t* a, const uint32_t* b) {
    asm("mma.sync.aligned.m16n8k16.row.col.f32.bf16.bf16.f32 "
        "{%0,%1,%2,%3}, {%4,%5,%6,%7}, {%8,%9}, {%0,%1,%2,%3};"
        : "+f"(d[0]), "+f"(d[1]), "+f"(d[2]), "+f"(d[3])
        : "r"(a[0]), "r"(a[1]), "r"(a[2]), "r"(a[3]), "r"(b[0]), "r"(b[1]));
}
__device__ __forceinline__ void mma16816h(float* d, const uint32_t* a, const uint32_t* b) {
    asm("mma.sync.aligned.m16n8k16.row.col.f32.f16.f16.f32 "
        "{%0,%1,%2,%3}, {%4,%5,%6,%7}, {%8,%9}, {%0,%1,%2,%3};"
        : "+f"(d[0]), "+f"(d[1]), "+f"(d[2]), "+f"(d[3])
        : "r"(a[0]), "r"(a[1]), "r"(a[2]), "r"(a[3]), "r"(b[0]), "r"(b[1]));
}
// f16 accumulator QK mma: D/C are f16x2 pairs
__device__ __forceinline__ void mma16816hh(uint32_t* d, const uint32_t* a, const uint32_t* b) {
    asm("mma.sync.aligned.m16n8k16.row.col.f16.f16.f16.f16 "
        "{%0,%1}, {%2,%3,%4,%5}, {%6,%7}, {%0,%1};"
        : "+r"(d[0]), "+r"(d[1])
        : "r"(a[0]), "r"(a[1]), "r"(a[2]), "r"(a[3]), "r"(b[0]), "r"(b[1]));
}
__device__ __forceinline__ uint32_t pkbf(float a, float b) {
    __nv_bfloat162 t = __floats2bfloat162_rn(a, b);
    return *reinterpret_cast<uint32_t*>(&t);
}
__device__ __forceinline__ uint32_t pkh(float a, float b) {
    __half2 t = __floats2half2_rn(a, b);
    return *reinterpret_cast<uint32_t*>(&t);
}
__device__ __forceinline__ uint32_t ex2h2(uint32_t x) {
    uint32_t r; asm("ex2.approx.f16x2 %0, %1;" : "=r"(r) : "r"(x)); return r;
}
__device__ __forceinline__ uint32_t hadd2(uint32_t a, uint32_t b) {
    uint32_t r; asm("add.rn.f16x2 %0, %1, %2;" : "=r"(r) : "r"(a), "r"(b)); return r;
}
__device__ __forceinline__ unsigned smemu(const void* p) {
    return (unsigned)__cvta_generic_to_shared(p);
}
__device__ __forceinline__ void cpa16(unsigned d, const void* s) {
    asm volatile("cp.async.cg.shared.global [%0], [%1], 16;" :: "r"(d), "l"(s));
}
__device__ __forceinline__ void cpcommit() { asm volatile("cp.async.commit_group;"); }
template<int N> __device__ __forceinline__ void cpwait() {
    asm volatile("cp.async.wait_group %0;" :: "n"(N));
}
__device__ __forceinline__ void ldmA(uint32_t& r0, uint32_t& r1, uint32_t& r2, uint32_t& r3, unsigned a) {
    asm volatile("ldmatrix.sync.aligned.m8n8.x4.shared.b16 {%0,%1,%2,%3}, [%4];"
        : "=r"(r0), "=r"(r1), "=r"(r2), "=r"(r3) : "r"(a));
}
__device__ __forceinline__ void ldmT(uint32_t& r0, uint32_t& r1, uint32_t& r2, uint32_t& r3, unsigned a) {
    asm volatile("ldmatrix.sync.aligned.m8n8.x4.trans.shared.b16 {%0,%1,%2,%3}, [%4];"
        : "=r"(r0), "=r"(r1), "=r"(r2), "=r"(r3) : "r"(a));
}

// ============== merged prologue ==============
// blocks [0,128): rope | [128,4224): weight cast | [4224,12416): cache2kv | [12416,14464): ln_to_kv
__global__ void __launch_bounds__(256)
prologue(const float* __restrict__ Wq, const float* __restrict__ Wk,
         const float* __restrict__ Wv, const float* __restrict__ Wo,
         const float* __restrict__ cache, float* __restrict__ out,
         const float* __restrict__ hidden, const float* __restrict__ ln_s,
         const float* __restrict__ ln_b) {
    const int blk = blockIdx.x, tid = threadIdx.x;
    __shared__ float sh[16];

    if (blk < 128) {
        int idx = blk * 256 + tid;
        int pos = idx >> 5, d = idx & 31;
        float fr = exp2f(-(float)d * (13.287712379549449f / 32.0f));
        float ang = (float)pos * fr;
        float s, c; sincosf(ang, &s, &c);
        g_rope[pos][2 * d]     = c;
        g_rope[pos][2 * d + 1] = s;
    } else if (blk < 4224) {
        // weight cast f32 -> bf16 (same [k][n] layout); 1024 blocks per weight
        int pb = blk - 128;
        const float* W; bf16* P;
        switch (pb >> 10) {
            case 0:  W = Wq; P = g_wq; break;
            case 1:  W = Wk; P = g_wk; break;
            case 2:  W = Wv; P = g_wv; break;
            default: W = Wo; P = g_wo; break;
        }
        int i = (pb & 1023) * 1024 + tid * 4;
        float4 a = *(const float4*)&W[i];
        *(uint2*)&P[i] = make_uint2(pkbf(a.x, a.y), pkbf(a.z, a.w));
    } else if (blk < 12416) {
        size_t i = ((size_t)(blk - 4224) * 256 + tid) * 4;
        int c = (int)(i & (HH - 1));
        int t = (int)((i >> 10) & (SS - 1));
        int b = (int)((i >> 20) & 1);
        int w = (int)(i >> 21);
        float4 v = *(const float4*)(cache + i);
        if (w >= 1) *(float4*)(out + i) = v;   // new_cache[w-1] = cache[w]
        bf16* dst = g_kv + ((size_t)b * LL + (size_t)w * SS + t) * HH + c;
        *(uint2*)dst = make_uint2(pkbf(v.x, v.y), pkbf(v.z, v.w));
    } else {
        int row = blk - 12416;
        int b = row >> 10, t = row & 1023;
        const float* xr = hidden + (size_t)row * HH;
        float4 v = *(const float4*)&xr[tid * 4];
        float s  = v.x + v.y + v.z + v.w;
        float ss = v.x * v.x + v.y * v.y + v.z * v.z + v.w * v.w;
#pragma unroll
        for (int o = 16; o > 0; o >>= 1) {
            s  += __shfl_xor_sync(0xffffffffu, s, o);
            ss += __shfl_xor_sync(0xffffffffu, ss, o);
        }
        if ((tid & 31) == 0) { sh[tid >> 5] = s; sh[(tid >> 5) + 8] = ss; }
        __syncthreads();
        float tot = 0.f, tots = 0.f;
#pragma unroll
        for (int i = 0; i < 8; i++) { tot += sh[i]; tots += sh[i + 8]; }
        float mu  = tot * (1.0f / HH);
        float inv = rsqrtf(tots * (1.0f / HH) - mu * mu + 1e-5f);
        float4 scv = *(const float4*)&ln_s[tid * 4];
        float4 biv = *(const float4*)&ln_b[tid * 4];
        float o0 = (v.x - mu) * inv * scv.x + biv.x;
        float o1 = (v.y - mu) * inv * scv.y + biv.y;
        float o2 = (v.z - mu) * inv * scv.z + biv.z;
        float o3 = (v.w - mu) * inv * scv.w + biv.w;
        bf16* dst = g_kv + ((size_t)b * LL + (size_t)WW * SS + t) * HH + tid * 4;
        *(uint2*)dst = make_uint2(pkbf(o0, o1), pkbf(o2, o3));
    }
}

// ---------------- LayerNorm(output) -> f32 ----------------
__global__ void ln_to_out(const float* __restrict__ x, const float* __restrict__ sc,
                          const float* __restrict__ bi, float* __restrict__ dst) {
    int row = blockIdx.x;
    const float* xr = x + (size_t)row * HH;
    int tid = threadIdx.x;
    float4 v = *(const float4*)&xr[tid * 4];
    float s  = v.x + v.y + v.z + v.w;
    float ss = v.x * v.x + v.y * v.y + v.z * v.z + v.w * v.w;
#pragma unroll
    for (int o = 16; o > 0; o >>= 1) {
        s  += __shfl_xor_sync(0xffffffffu, s, o);
        ss += __shfl_xor_sync(0xffffffffu, ss, o);
    }
    __shared__ float sh[16];
    if ((tid & 31) == 0) { sh[tid >> 5] = s; sh[(tid >> 5) + 8] = ss; }
    __syncthreads();
    float tot = 0.f, tots = 0.f;
#pragma unroll
    for (int i = 0; i < 8; i++) { tot += sh[i]; tots += sh[i + 8]; }
    float mu  = tot * (1.0f / HH);
    float inv = rsqrtf(tots * (1.0f / HH) - mu * mu + 1e-5f);
    float4 scv = *(const float4*)&sc[tid * 4];
    float4 biv = *(const float4*)&bi[tid * 4];
    float4 ov;
    ov.x = (v.x - mu) * inv * scv.x + biv.x;
    ov.y = (v.y - mu) * inv * scv.y + biv.y;
    ov.z = (v.z - mu) * inv * scv.z + biv.z;
    ov.w = (v.w - mu) * inv * scv.w + biv.w;
    *(float4*)(dst + (size_t)row * HH + tid * 4) = ov;
}

// ===================== GEMM mainloop: BM=MT*64, BN=128, BK=64, 3-stage =====================
// B operand now bf16 [k][n] in smem (272 B row stride), fragments via ldmatrix.trans
// — replaces 64 scalar LDS.32 per k-iter with 16 LDSM (kills the LSU co-limit).
#define GE_BS_STRIDE 17408   /* 64 rows x 272 B */

template<int MT>   // MT m-subtiles of 16 rows per warp; BM = MT*64
struct GemmCore {
    static constexpr int AS_STRIDE = MT * 64 * 144;
    float acc[MT][8][4];
    __device__ __forceinline__ void run(const bf16* __restrict__ A,
                                        const bf16* __restrict__ Wb,
                                        int bm, int bn, char* sm) {
        const unsigned smA = smemu(sm);
        const unsigned smB = smA + 3 * AS_STRIDE;
        const int tid = threadIdx.x, warp = tid >> 5, lane = tid & 31;
        const int wm = (warp >> 1) * (MT * 16), wn = (warp & 1) * 64;
#pragma unroll
        for (int a = 0; a < MT; a++)
#pragma unroll
            for (int b = 0; b < 8; b++)
#pragma unroll
                for (int c = 0; c < 4; c++) acc[a][b][c] = 0.f;

        const int aRow = (lane & 7) + ((lane & 8) ? 8 : 0);
        const int aCol = (lane & 16) ? 8 : 0;
        const unsigned aAddr = smA + (wm + aRow) * 144 + aCol * 2;
        const int bRow = lane & 15;                 // k offset within 16
        const int bCol = (lane & 16) ? 8 : 0;       // n offset (0/8)
        const unsigned bAddr = smB + bRow * 272 + (wn + bCol) * 2;

        auto load_stage = [&](int st, int kb) {
#pragma unroll
            for (int p = 0; p < MT * 2; p++) {
                int id = tid + p * 256;
                int r = id >> 3, c = id & 7;
                cpa16(smA + st * AS_STRIDE + r * 144 + c * 16,
                      &A[(size_t)(bm + r) * HH + kb + c * 8]);
            }
#pragma unroll
            for (int p = 0; p < 4; p++) {
                int id = tid + p * 256;
                int r = id >> 4, c = id & 15;       // 64 k-rows x 16 chunks of 16B
                cpa16(smB + st * GE_BS_STRIDE + r * 272 + c * 16,
                      &Wb[(size_t)(kb + r) * HH + bn + c * 8]);
            }
            cpcommit();
        };

        load_stage(0, 0);

        for (int it = 0; it < 16; ++it) {
            const int s = it - 3 * ((it * 0x5556) >> 16);  // it % 3
            if (it < 15) {
                load_stage((it + 1) % 3, (it + 1) * 64);
                cpwait<1>();
            } else {
                cpwait<0>();
            }
            __syncthreads();
            const unsigned aSt = aAddr + s * AS_STRIDE;
            const unsigned bSt = bAddr + s * GE_BS_STRIDE;
#pragma unroll
            for (int ks = 0; ks < 4; ks++) {
                uint32_t af[MT][4];
#pragma unroll
                for (int mt = 0; mt < MT; mt++) {
                    ldmA(af[mt][0], af[mt][1], af[mt][2], af[mt][3],
                         aSt + mt * 16 * 144 + ks * 16 * 2);
                }
#pragma unroll
                for (int np = 0; np < 4; np++) {
                    uint32_t r0, r1, r2, r3;
                    ldmT(r0, r1, r2, r3, bSt + ks * 16 * 272 + np * 32);
                    uint32_t b0[2] = { r0, r1 };
                    uint32_t b1[2] = { r2, r3 };
#pragma unroll
                    for (int mt = 0; mt < MT; mt++) {
                        mma16816(acc[mt][np * 2],     af[mt], b0);
                        mma16816(acc[mt][np * 2 + 1], af[mt], b1);
                    }
                }
            }
        }
    }
};

#define GE_SMEM2 (3 * (2*64*144) + 3 * GE_BS_STRIDE)   /* 107520 for MT=2 */
#define GE_SMEM1 (3 * (1*64*144) + 3 * GE_BS_STRIDE)   /*  79872 for MT=1 */

// ---------------- fused QKV projection ----------------
__global__ void __launch_bounds__(256, 2)
qkv_gemm(const bf16* __restrict__ kv) {
    extern __shared__ char sm[];
    const int bidx = blockIdx.z;
    const int y = blockIdx.y;
    int mode, ylocal;
    if (y < 40)      { mode = 0; ylocal = y; }
    else if (y < 80) { mode = 1; ylocal = y - 40; }
    else             { mode = 2; ylocal = y - 80; }
    const bf16* W2 = (mode == 0) ? g_wk : (mode == 1) ? g_wv : g_wq;
    const bf16* A = kv + (size_t)bidx * LL * HH + (mode == 2 ? (size_t)WW * SS * HH : 0);
    const int bm = ylocal * 128, bn = blockIdx.x * 128;

    GemmCore<2> core;
    core.run(A, W2, bm, bn, sm);

    const int tid = threadIdx.x, warp = tid >> 5, lane = tid & 31;
    const int g = lane >> 2, tg = lane & 3;
    const int wm = (warp >> 1) * 32, wn = (warp & 1) * 64;
    const int Lr = (mode == 2) ? SS : LL;
    const int hd = (bn + wn) >> 6;
    const float QS = 0.18033688011112042f;  // (1/8)*log2(e)

#pragma unroll
    for (int mt = 0; mt < 2; mt++) {
#pragma unroll
        for (int half = 0; half < 2; half++) {
            int r = bm + wm + mt * 16 + g + half * 8;
            if (mode == 1) {
                __half* rowp = g_vh + (((size_t)(bidx * NHH + hd)) * LL + r) * HDD;
#pragma unroll
                for (int nt = 0; nt < 8; nt++) {
                    int d = nt * 8 + tg * 2;
                    *(uint32_t*)&rowp[d] =
                        pkh(core.acc[mt][nt][half * 2], core.acc[mt][nt][half * 2 + 1]);
                }
            } else {
                __half* rowp = ((mode == 0) ? g_kh : g_qh)
                               + (((size_t)(bidx * NHH + hd)) * Lr + r) * HDD;
                int pos = r & 1023;
                const float* rp = &g_rope[pos][0];
#pragma unroll
                for (int nt = 0; nt < 4; nt++) {
                    int d = nt * 8 + tg * 2;
                    float4 cs = *(const float4*)&rp[d * 2];
                    float x10 = core.acc[mt][nt][half * 2],     x11 = core.acc[mt][nt][half * 2 + 1];
                    float x20 = core.acc[mt][nt + 4][half * 2], x21 = core.acc[mt][nt + 4][half * 2 + 1];
                    float o00 = x10 * cs.x - x20 * cs.y;
                    float o10 = x10 * cs.y + x20 * cs.x;
                    float o01 = x11 * cs.z - x21 * cs.w;
                    float o11 = x11 * cs.w + x21 * cs.z;
                    if (mode == 2) { o00 *= QS; o01 *= QS; o10 *= QS; o11 *= QS; }
                    *(uint32_t*)&rowp[d]      = pkh(o00, o01);
                    *(uint32_t*)&rowp[d + 32] = pkh(o10, o11);
                }
            }
        }
    }
}

// ---------------- O projection + gated residual + layer scale (BM=64) ----------------
__global__ void __launch_bounds__(256, 2)
gemm_o(const bf16* __restrict__ A, float* __restrict__ out,
       const float* __restrict__ hid, const float* __restrict__ c3,
       const float* __restrict__ gate, const float* __restrict__ ls) {
    extern __shared__ char sm[];
    const int bm = blockIdx.y * 64, bn = blockIdx.x * 128;
    GemmCore<1> core;
    core.run(A, g_wo, bm, bn, sm);

    const int tid = threadIdx.x, warp = tid >> 5, lane = tid & 31;
    const int g = lane >> 2, tg = lane & 3;
    const int wm = (warp >> 1) * 16, wn = (warp & 1) * 64;
    float gs[8][2], lv[8][2];
#pragma unroll
    for (int nt = 0; nt < 8; nt++) {
        int c = bn + wn + nt * 8 + tg * 2;
        float2 gv = *(const float2*)&gate[c];
        float2 l2 = *(const float2*)&ls[c];
        gs[nt][0] = 1.f / (1.f + __expf(-gv.x));
        gs[nt][1] = 1.f / (1.f + __expf(-gv.y));
        lv[nt][0] = l2.x; lv[nt][1] = l2.y;
    }
#pragma unroll
    for (int half = 0; half < 2; half++) {
        int r = bm + wm + g + half * 8;
#pragma unroll
        for (int nt = 0; nt < 8; nt++) {
            int c = bn + wn + nt * 8 + tg * 2;
            size_t idx = (size_t)r * HH + c;
            float a0 = core.acc[0][nt][half * 2], a1 = core.acc[0][nt][half * 2 + 1];
            float2 hv = *(const float2*)&hid[idx];
            float2 cv = *(const float2*)&c3[idx];
            float2 ov;
            ov.x = hv.x + lv[nt][0] * (gs[nt][0] * a0 + (1.f - gs[nt][0]) * cv.x);
            ov.y = hv.y + lv[nt][1] * (gs[nt][1] * a1 + (1.f - gs[nt][1]) * cv.y);
            *(float2*)&out[idx] = ov;
        }
    }
}

// ---------------- flash attention: BM=256, 16 warps, 6-stage ring, cross-tile pipelined,
//                  f16-accumulated QK (sacc f16x2 -> ex2h2 directly) ----------------
#define FL_ST 9216                  /* 64 x 144 B per tensor per stage */
#define FL_SMEM (12 * FL_ST)        /* 110592 */
#define FL_TILES (LL / 64)          /* 80 */

__global__ void __launch_bounds__(512, 1) flash_attn() {
    extern __shared__ char sm[];
    const int b = blockIdx.z, h = blockIdx.y, q0 = blockIdx.x * 256;
    const __half* Qp = g_qh + ((size_t)(b * NHH + h)) * SS * HDD;
    const __half* Kp = g_kh + ((size_t)(b * NHH + h)) * LL * HDD;
    const __half* Vp = g_vh + ((size_t)(b * NHH + h)) * LL * HDD;
    const unsigned smK = smemu(sm);
    const unsigned smV = smK + 6 * FL_ST;
    const int tid = threadIdx.x, warp = tid >> 5, lane = tid & 31;
    const int g = lane >> 2, tg = lane & 3;
    const int kRow = (lane & 7) + ((lane & 16) ? 8 : 0);
    const int kCol = (lane & 8);
    const int vRow = lane & 15;
    const int vCol = (lane & 16) ? 8 : 0;
    const unsigned kAddr = smK + kRow * 144 + kCol * 2;
    const unsigned vAddr = smV + vRow * 144 + vCol * 2;

    uint32_t qf[4][4];
    {
        int r = q0 + warp * 16 + g;
#pragma unroll
        for (int kt = 0; kt < 4; kt++) {
            qf[kt][0] = *(const uint32_t*)&Qp[(size_t)r * HDD + kt * 16 + tg * 2];
            qf[kt][1] = *(const uint32_t*)&Qp[(size_t)(r + 8) * HDD + kt * 16 + tg * 2];
            qf[kt][2] = *(const uint32_t*)&Qp[(size_t)r * HDD + kt * 16 + 8 + tg * 2];
            qf[kt][3] = *(const uint32_t*)&Qp[(size_t)(r + 8) * HDD + kt * 16 + 8 + tg * 2];
        }
    }
    float l0 = 0.f, l1 = 0.f;
    float o[8][4];
#pragma unroll
    for (int nt = 0; nt < 8; nt++)
#pragma unroll
        for (int i = 0; i < 4; i++) o[nt][i] = 0.f;
    uint32_t pf[4][4];   // P fragments (current tile), live across iterations

    auto load_kv = [&](int st, int j) {
        const __half* Kt = Kp + (size_t)j * 64 * HDD;
        const __half* Vt = Vp + (size_t)j * 64 * HDD;
        int r = tid >> 3, c = tid & 7;
        cpa16(smK + st * FL_ST + r * 144 + c * 16, Kt + (size_t)r * HDD + c * 8);
        cpa16(smV + st * FL_ST + r * 144 + c * 16, Vt + (size_t)r * HDD + c * 8);
        cpcommit();
    };

    auto qk = [&](int s, uint32_t sacc2[8][2]) {
        const unsigned kSt = kAddr + s * FL_ST;
#pragma unroll
        for (int kt = 0; kt < 4; kt++) {
            const int k0 = kt * 16;
#pragma unroll
            for (int np = 0; np < 4; np++) {
                uint32_t r0, r1, r2, r3;
                ldmA(r0, r1, r2, r3, kSt + np * 16 * 144 + k0 * 2);
                uint32_t b0[2] = { r0, r1 };
                uint32_t b1[2] = { r2, r3 };
                mma16816hh(sacc2[np * 2], qf[kt], b0);
                mma16816hh(sacc2[np * 2 + 1], qf[kt], b1);
            }
        }
    };
    auto pv = [&](int s) {
        const unsigned vSt = vAddr + s * FL_ST;
#pragma unroll
        for (int kt = 0; kt < 4; kt++) {
            const int k0 = kt * 16;
#pragma unroll
            for (int np = 0; np < 4; np++) {
                uint32_t r0, r1, r2, r3;
                ldmT(r0, r1, r2, r3, vSt + k0 * 144 + np * 16 * 2);
                uint32_t b0[2] = { r0, r1 };
                uint32_t b1[2] = { r2, r3 };
                mma16816h(o[np * 2], pf[kt], b0);
                mma16816h(o[np * 2 + 1], pf[kt], b1);
            }
        }
    };
    auto softmax = [&](const uint32_t sacc2[8][2]) {
#pragma unroll
        for (int nt = 0; nt < 8; nt++) {
            pf[nt >> 1][(nt & 1) * 2 + 0] = ex2h2(sacc2[nt][0]);
            pf[nt >> 1][(nt & 1) * 2 + 1] = ex2h2(sacc2[nt][1]);
        }
        uint32_t s0 = hadd2(hadd2(hadd2(pf[0][0], pf[1][0]), hadd2(pf[2][0], pf[3][0])),
                            hadd2(hadd2(pf[0][2], pf[1][2]), hadd2(pf[2][2], pf[3][2])));
        uint32_t s1 = hadd2(hadd2(hadd2(pf[0][1], pf[1][1]), hadd2(pf[2][1], pf[3][1])),
                            hadd2(hadd2(pf[0][3], pf[1][3]), hadd2(pf[2][3], pf[3][3])));
        __half2 h0 = *reinterpret_cast<__half2*>(&s0);
        __half2 h1 = *reinterpret_cast<__half2*>(&s1);
        l0 += __low2float(h0) + __high2float(h0);
        l1 += __low2float(h1) + __high2float(h1);
    };

    // prefetch tiles 0..3 into stages 0..3
#pragma unroll
    for (int j = 0; j < 4; j++) load_kv(j, j);

    // tile 0: S + softmax (no PV yet)
    cpwait<3>();
    __syncthreads();
    {
        uint32_t sacc2[8][2];
#pragma unroll
        for (int nt = 0; nt < 8; nt++) { sacc2[nt][0] = 0; sacc2[nt][1] = 0; }
        qk(0, sacc2);
        softmax(sacc2);
    }

    // main: iteration j computes QK(j+1) + PV(j), then softmax(j+1)
    for (int j = 0; j < FL_TILES - 1; j++) {
        if (j + 4 < FL_TILES) {
            load_kv((j + 4) % 6, j + 4);   // stage (j-2)%6: fully read in iter j-2
            cpwait<3>();                    // tiles <= j+1 complete
        } else if (j + 4 == FL_TILES)     { cpwait<2>(); }
        else if (j + 3 == FL_TILES)       { cpwait<1>(); }
        else                              { cpwait<0>(); }
        __syncthreads();

        uint32_t sacc2[8][2];
#pragma unroll
        for (int nt = 0; nt < 8; nt++) { sacc2[nt][0] = 0; sacc2[nt][1] = 0; }
        qk((j + 1) % 6, sacc2);   // independent of pf
        pv(j % 6);                // uses pf (tile j)
        softmax(sacc2);           // pf <- tile j+1
    }

    // final PV for tile 79
    pv((FL_TILES - 1) % 6);

    // final row-sum reduce
    l0 += __shfl_xor_sync(0xffffffffu, l0, 1);
    l0 += __shfl_xor_sync(0xffffffffu, l0, 2);
    l1 += __shfl_xor_sync(0xffffffffu, l1, 1);
    l1 += __shfl_xor_sync(0xffffffffu, l1, 2);

    float il0 = 1.f / l0, il1 = 1.f / l1;
    int r = b * SS + q0 + warp * 16 + g;
    bf16* cp  = g_ctx + (size_t)r * HH + h * HDD;
    bf16* cp8 = g_ctx + (size_t)(r + 8) * HH + h * HDD;
#pragma unroll
    for (int nt = 0; nt < 8; nt++) {
        int c = nt * 8 + tg * 2;
        *(uint32_t*)&cp[c]  = pkbf(o[nt][0] * il0, o[nt][1] * il0);
        *(uint32_t*)&cp8[c] = pkbf(o[nt][2] * il1, o[nt][3] * il1);
    }
}

// ---------------- launch ----------------
extern "C" void kernel_launch(void* const* d_in, const int* in_sizes, int n_in,
                              void* d_out, int out_size) {
    const float* hidden = (const float*)d_in[0];
    const float* cache  = (const float*)d_in[1];
    const float* ln_s   = (const float*)d_in[2];
    const float* ln_b   = (const float*)d_in[3];
    const float* Wq     = (const float*)d_in[4];
    const float* Wk     = (const float*)d_in[5];
    const float* Wv     = (const float*)d_in[6];
    const float* Wo     = (const float*)d_in[7];
    const float* gate   = (const float*)d_in[8];
    const float* ls     = (const float*)d_in[9];
    float* out = (float*)d_out;

    void* p_kv; void* p_ctx;
    cudaGetSymbolAddress(&p_kv, g_kv);
    cudaGetSymbolAddress(&p_ctx, g_ctx);

    cudaFuncSetAttribute(qkv_gemm,   cudaFuncAttributeMaxDynamicSharedMemorySize, GE_SMEM2);
    cudaFuncSetAttribute(gemm_o,     cudaFuncAttributeMaxDynamicSharedMemorySize, GE_SMEM1);
    cudaFuncSetAttribute(flash_attn, cudaFuncAttributeMaxDynamicSharedMemorySize, FL_SMEM);

    prologue<<<14464, 256>>>(Wq, Wk, Wv, Wo, cache, out, hidden, ln_s, ln_b);

    qkv_gemm<<<dim3(8, 88, BB), 256, GE_SMEM2>>>((const bf16*)p_kv);

    flash_attn<<<dim3(SS / 256, NHH, BB), 512, FL_SMEM>>>();

    gemm_o<<<dim3(8, 32), 256, GE_SMEM1>>>((const bf16*)p_ctx, out, hidden,
                                           cache + (size_t)3 * BB * SS * HH, gate, ls);

    ln_to_out<<<BB * SS, 256>>>(out, ln_s, ln_b, out + (size_t)WW * BB * SS * HH);
}

// round 17
// speedup vs baseline: 1.5346x; 1.5346x over previous
#include <cuda_runtime.h>
#include <cuda_bf16.h>
#include <cuda_fp16.h>
#include <cstdint>

typedef __nv_bfloat16 bf16;

#define BB  2
#define SS  1024
#define HH  1024
#define NHH 16
#define HDD 64
#define WW  4
#define LL  5120   /* (W+1)*S */

// ---------------- scratch (device globals) ----------------
__device__ bf16     g_kv[(size_t)BB*LL*HH];
__device__ uint32_t g_wq[HH*HH/2], g_wk[HH*HH/2], g_wv[HH*HH/2], g_wo[HH*HH/2];
__device__ bf16     g_qh[(size_t)BB*NHH*SS*HDD];
__device__ bf16     g_kh[(size_t)BB*NHH*LL*HDD];
__device__ __half   g_vh[(size_t)BB*NHH*LL*HDD];
__device__ bf16     g_ctx[(size_t)BB*SS*HH];
__device__ float    g_rope[SS][2*32];

// ---------------- helpers ----------------
__device__ __forceinline__ void mma16816(float* d, const uint32_t* a, const uint32_t* b) {
    asm("mma.sync.aligned.m16n8k16.row.col.f32.bf16.bf16.f32 "
        "{%0,%1,%2,%3}, {%4,%5,%6,%7}, {%8,%9}, {%0,%1,%2,%3};"
        : "+f"(d[0]), "+f"(d[1]), "+f"(d[2]), "+f"(d[3])
        : "r"(a[0]), "r"(a[1]), "r"(a[2]), "r"(a[3]), "r"(b[0]), "r"(b[1]));
}
__device__ __forceinline__ void mma16816h(float* d, const uint32_t* a, const uint32_t* b) {
    asm("mma.sync.aligned.m16n8k16.row.col.f32.f16.f16.f32 "
        "{%0,%1,%2,%3}, {%4,%5,%6,%7}, {%8,%9}, {%0,%1,%2,%3};"
        : "+f"(d[0]), "+f"(d[1]), "+f"(d[2]), "+f"(d[3])
        : "r"(a[0]), "r"(a[1]), "r"(a[2]), "r"(a[3]), "r"(b[0]), "r"(b[1]));
}
__device__ __forceinline__ uint32_t pkbf(float a, float b) {
    __nv_bfloat162 t = __floats2bfloat162_rn(a, b);
    return *reinterpret_cast<uint32_t*>(&t);
}
__device__ __forceinline__ uint32_t pkh(float a, float b) {
    __half2 t = __floats2half2_rn(a, b);
    return *reinterpret_cast<uint32_t*>(&t);
}
__device__ __forceinline__ uint32_t cvth2(float hi, float lo) {
    uint32_t r; asm("cvt.rn.f16x2.f32 %0, %1, %2;" : "=r"(r) : "f"(hi), "f"(lo)); return r;
}
__device__ __forceinline__ uint32_t ex2h2(uint32_t x) {
    uint32_t r; asm("ex2.approx.f16x2 %0, %1;" : "=r"(r) : "r"(x)); return r;
}
__device__ __forceinline__ uint32_t hadd2(uint32_t a, uint32_t b) {
    uint32_t r; asm("add.rn.f16x2 %0, %1, %2;" : "=r"(r) : "r"(a), "r"(b)); return r;
}
__device__ __forceinline__ unsigned smemu(const void* p) {
    return (unsigned)__cvta_generic_to_shared(p);
}
__device__ __forceinline__ void cpa16(unsigned d, const void* s) {
    asm volatile("cp.async.cg.shared.global [%0], [%1], 16;" :: "r"(d), "l"(s));
}
__device__ __forceinline__ void cpcommit() { asm volatile("cp.async.commit_group;"); }
template<int N> __device__ __forceinline__ void cpwait() {
    asm volatile("cp.async.wait_group %0;" :: "n"(N));
}
__device__ __forceinline__ void ldmA(uint32_t& r0, uint32_t& r1, uint32_t& r2, uint32_t& r3, unsigned a) {
    asm volatile("ldmatrix.sync.aligned.m8n8.x4.shared.b16 {%0,%1,%2,%3}, [%4];"
        : "=r"(r0), "=r"(r1), "=r"(r2), "=r"(r3) : "r"(a));
}
__device__ __forceinline__ void ldmT(uint32_t& r0, uint32_t& r1, uint32_t& r2, uint32_t& r3, unsigned a) {
    asm volatile("ldmatrix.sync.aligned.m8n8.x4.trans.shared.b16 {%0,%1,%2,%3}, [%4];"
        : "=r"(r0), "=r"(r1), "=r"(r2), "=r"(r3) : "r"(a));
}

// ============== merged prologue ==============
// blocks [0,128): rope | [128,2176): pack_w | [2176,10368): cache2kv | [10368,12416): ln_to_kv
__global__ void __launch_bounds__(256)
prologue(const float* __restrict__ Wq, const float* __restrict__ Wk,
         const float* __restrict__ Wv, const float* __restrict__ Wo,
         const float* __restrict__ cache, float* __restrict__ out,
         const float* __restrict__ hidden, const float* __restrict__ ln_s,
         const float* __restrict__ ln_b) {
    const int blk = blockIdx.x, tid = threadIdx.x;
    __shared__ float sh[16];

    if (blk < 128) {
        int idx = blk * 256 + tid;
        int pos = idx >> 5, d = idx & 31;
        float fr = exp2f(-(float)d * (13.287712379549449f / 32.0f));
        float ang = (float)pos * fr;
        float s, c; sincosf(ang, &s, &c);
        g_rope[pos][2 * d]     = c;
        g_rope[pos][2 * d + 1] = s;
    } else if (blk < 2176) {
        int pb = blk - 128;
        const float* W; uint32_t* P;
        switch (pb >> 9) {
            case 0:  W = Wq; P = g_wq; break;
            case 1:  W = Wk; P = g_wk; break;
            case 2:  W = Wv; P = g_wv; break;
            default: W = Wo; P = g_wo; break;
        }
        int i = (pb & 511) * 256 + tid;
        int kp = i >> 8, n0 = (i & 255) * 4;
        float4 a = *(const float4*)&W[(size_t)(2 * kp) * HH + n0];
        float4 b = *(const float4*)&W[(size_t)(2 * kp + 1) * HH + n0];
        uint4 o;
        o.x = pkbf(a.x, b.x); o.y = pkbf(a.y, b.y);
        o.z = pkbf(a.z, b.z); o.w = pkbf(a.w, b.w);
        *(uint4*)&P[(size_t)kp * HH + n0] = o;
    } else if (blk < 10368) {
        size_t i = ((size_t)(blk - 2176) * 256 + tid) * 4;
        int c = (int)(i & (HH - 1));
        int t = (int)((i >> 10) & (SS - 1));
        int b = (int)((i >> 20) & 1);
        int w = (int)(i >> 21);
        float4 v = *(const float4*)(cache + i);
        if (w >= 1) *(float4*)(out + i) = v;   // new_cache[w-1] = cache[w]
        bf16* dst = g_kv + ((size_t)b * LL + (size_t)w * SS + t) * HH + c;
        *(uint2*)dst = make_uint2(pkbf(v.x, v.y), pkbf(v.z, v.w));
    } else {
        int row = blk - 10368;
        int b = row >> 10, t = row & 1023;
        const float* xr = hidden + (size_t)row * HH;
        float4 v = *(const float4*)&xr[tid * 4];
        float s  = v.x + v.y + v.z + v.w;
        float ss = v.x * v.x + v.y * v.y + v.z * v.z + v.w * v.w;
#pragma unroll
        for (int o = 16; o > 0; o >>= 1) {
            s  += __shfl_xor_sync(0xffffffffu, s, o);
            ss += __shfl_xor_sync(0xffffffffu, ss, o);
        }
        if ((tid & 31) == 0) { sh[tid >> 5] = s; sh[(tid >> 5) + 8] = ss; }
        __syncthreads();
        float tot = 0.f, tots = 0.f;
#pragma unroll
        for (int i = 0; i < 8; i++) { tot += sh[i]; tots += sh[i + 8]; }
        float mu  = tot * (1.0f / HH);
        float inv = rsqrtf(tots * (1.0f / HH) - mu * mu + 1e-5f);
        float4 scv = *(const float4*)&ln_s[tid * 4];
        float4 biv = *(const float4*)&ln_b[tid * 4];
        float o0 = (v.x - mu) * inv * scv.x + biv.x;
        float o1 = (v.y - mu) * inv * scv.y + biv.y;
        float o2 = (v.z - mu) * inv * scv.z + biv.z;
        float o3 = (v.w - mu) * inv * scv.w + biv.w;
        bf16* dst = g_kv + ((size_t)b * LL + (size_t)WW * SS + t) * HH + tid * 4;
        *(uint2*)dst = make_uint2(pkbf(o0, o1), pkbf(o2, o3));
    }
}

// ---------------- LayerNorm(output) -> f32 ----------------
__global__ void ln_to_out(const float* __restrict__ x, const float* __restrict__ sc,
                          const float* __restrict__ bi, float* __restrict__ dst) {
    int row = blockIdx.x;
    const float* xr = x + (size_t)row * HH;
    int tid = threadIdx.x;
    float4 v = *(const float4*)&xr[tid * 4];
    float s  = v.x + v.y + v.z + v.w;
    float ss = v.x * v.x + v.y * v.y + v.z * v.z + v.w * v.w;
#pragma unroll
    for (int o = 16; o > 0; o >>= 1) {
        s  += __shfl_xor_sync(0xffffffffu, s, o);
        ss += __shfl_xor_sync(0xffffffffu, ss, o);
    }
    __shared__ float sh[16];
    if ((tid & 31) == 0) { sh[tid >> 5] = s; sh[(tid >> 5) + 8] = ss; }
    __syncthreads();
    float tot = 0.f, tots = 0.f;
#pragma unroll
    for (int i = 0; i < 8; i++) { tot += sh[i]; tots += sh[i + 8]; }
    float mu  = tot * (1.0f / HH);
    float inv = rsqrtf(tots * (1.0f / HH) - mu * mu + 1e-5f);
    float4 scv = *(const float4*)&sc[tid * 4];
    float4 biv = *(const float4*)&bi[tid * 4];
    float4 ov;
    ov.x = (v.x - mu) * inv * scv.x + biv.x;
    ov.y = (v.y - mu) * inv * scv.y + biv.y;
    ov.z = (v.z - mu) * inv * scv.z + biv.z;
    ov.w = (v.w - mu) * inv * scv.w + biv.w;
    *(float4*)(dst + (size_t)row * HH + tid * 4) = ov;
}

// ===================== GEMM mainloop: BM=MT*64, BN=NT*16, BK=64, 3-stage =====================
// Packed-pair bf16x2 B operand in smem (scalar LDS.32 fragments — the measured-fastest path).
template<int MT, int NT>   // MT: m-subtiles of 16/warp; NT: n-subtiles of 8/warp (BN = NT*16)
struct GemmCore {
    static constexpr int AS_STRIDE = MT * 64 * 144;
    static constexpr int BS_W = NT * 16 + 8;           // u32 row width incl pad
    static constexpr int BS_STRIDE = 32 * BS_W * 4;    // bytes per stage
    float acc[MT][NT][4];
    __device__ __forceinline__ void run(const bf16* __restrict__ A,
                                        const uint32_t* __restrict__ W2,
                                        int bm, int bn, char* sm) {
        const unsigned smA = smemu(sm);
        const unsigned smB = smA + 3 * AS_STRIDE;
        char* smBgen = sm + 3 * AS_STRIDE;
        const int tid = threadIdx.x, warp = tid >> 5, lane = tid & 31;
        const int tg = lane & 3;
        const int wm = (warp >> 1) * (MT * 16), wn = (warp & 1) * (NT * 8);
#pragma unroll
        for (int a = 0; a < MT; a++)
#pragma unroll
            for (int b = 0; b < NT; b++)
#pragma unroll
                for (int c = 0; c < 4; c++) acc[a][b][c] = 0.f;

        const int aRow = (lane & 7) + ((lane & 8) ? 8 : 0);
        const int aCol = (lane & 16) ? 8 : 0;
        const unsigned aAddr = smA + (wm + aRow) * 144 + aCol * 2;

        auto load_stage = [&](int st, int kb) {
#pragma unroll
            for (int p = 0; p < MT * 2; p++) {
                int id = tid + p * 256;
                int r = id >> 3, c = id & 7;
                cpa16(smA + st * AS_STRIDE + r * 144 + c * 16,
                      &A[(size_t)(bm + r) * HH + kb + c * 8]);
            }
#pragma unroll
            for (int p = 0; p < NT / 2; p++) {
                int id = tid + p * 256;
                int r = id / (NT * 4), c = id % (NT * 4);
                cpa16(smB + st * BS_STRIDE + r * BS_W * 4 + c * 16,
                      &W2[(size_t)((kb >> 1) + r) * HH + bn + c * 4]);
            }
            cpcommit();
        };

        load_stage(0, 0);

        for (int it = 0; it < 16; ++it) {
            const int s = it - 3 * ((it * 0x5556) >> 16);  // it % 3
            if (it < 15) {
                load_stage((it + 1) % 3, (it + 1) * 64);
                cpwait<1>();
            } else {
                cpwait<0>();
            }
            __syncthreads();
            const uint32_t* BsP = (const uint32_t*)(smBgen + s * BS_STRIDE);
            const unsigned aSt = aAddr + s * AS_STRIDE;
#pragma unroll
            for (int ks = 0; ks < 4; ks++) {
                uint32_t af[MT][4];
#pragma unroll
                for (int mt = 0; mt < MT; mt++) {
                    ldmA(af[mt][0], af[mt][1], af[mt][2], af[mt][3],
                         aSt + mt * 16 * 144 + ks * 16 * 2);
                }
#pragma unroll
                for (int nt = 0; nt < NT; nt++) {
                    int col = wn + nt * 8 + (lane >> 2);
                    uint32_t bb[2];
                    bb[0] = BsP[(ks * 8 + tg) * BS_W + col];
                    bb[1] = BsP[(ks * 8 + 4 + tg) * BS_W + col];
#pragma unroll
                    for (int mt = 0; mt < MT; mt++)
                        mma16816(acc[mt][nt], af[mt], bb);
                }
            }
        }
    }
};

#define GE_SMEM_QKV (3 * (2*64*144) + 3 * (32*136*4))   /* 107520: MT=2 NT=8 */
#define GE_SMEM_O   (3 * (2*64*144) + 3 * (32*72*4))    /*  82944: MT=2 NT=4 */

// ---------------- fused QKV projection ----------------
__global__ void __launch_bounds__(256, 2)
qkv_gemm(const bf16* __restrict__ kv) {
    extern __shared__ char sm[];
    const int bidx = blockIdx.z;
    const int y = blockIdx.y;
    int mode, ylocal;
    if (y < 40)      { mode = 0; ylocal = y; }
    else if (y < 80) { mode = 1; ylocal = y - 40; }
    else             { mode = 2; ylocal = y - 80; }
    const uint32_t* W2 = (mode == 0) ? g_wk : (mode == 1) ? g_wv : g_wq;
    const bf16* A = kv + (size_t)bidx * LL * HH + (mode == 2 ? (size_t)WW * SS * HH : 0);
    const int bm = ylocal * 128, bn = blockIdx.x * 128;

    GemmCore<2, 8> core;
    core.run(A, W2, bm, bn, sm);

    const int tid = threadIdx.x, warp = tid >> 5, lane = tid & 31;
    const int g = lane >> 2, tg = lane & 3;
    const int wm = (warp >> 1) * 32, wn = (warp & 1) * 64;
    const int Lr = (mode == 2) ? SS : LL;
    const int hd = (bn + wn) >> 6;
    const float QS = 0.18033688011112042f;  // (1/8)*log2(e)

#pragma unroll
    for (int mt = 0; mt < 2; mt++) {
#pragma unroll
        for (int half = 0; half < 2; half++) {
            int r = bm + wm + mt * 16 + g + half * 8;
            if (mode == 1) {
                __half* rowp = g_vh + (((size_t)(bidx * NHH + hd)) * LL + r) * HDD;
#pragma unroll
                for (int nt = 0; nt < 8; nt++) {
                    int d = nt * 8 + tg * 2;
                    *(uint32_t*)&rowp[d] =
                        pkh(core.acc[mt][nt][half * 2], core.acc[mt][nt][half * 2 + 1]);
                }
            } else {
                bf16* rowp = ((mode == 0) ? g_kh : g_qh)
                             + (((size_t)(bidx * NHH + hd)) * Lr + r) * HDD;
                int pos = r & 1023;
                const float* rp = &g_rope[pos][0];
#pragma unroll
                for (int nt = 0; nt < 4; nt++) {
                    int d = nt * 8 + tg * 2;
                    float4 cs = *(const float4*)&rp[d * 2];
                    float x10 = core.acc[mt][nt][half * 2],     x11 = core.acc[mt][nt][half * 2 + 1];
                    float x20 = core.acc[mt][nt + 4][half * 2], x21 = core.acc[mt][nt + 4][half * 2 + 1];
                    float o00 = x10 * cs.x - x20 * cs.y;
                    float o10 = x10 * cs.y + x20 * cs.x;
                    float o01 = x11 * cs.z - x21 * cs.w;
                    float o11 = x11 * cs.w + x21 * cs.z;
                    if (mode == 2) { o00 *= QS; o01 *= QS; o10 *= QS; o11 *= QS; }
                    *(uint32_t*)&rowp[d]      = pkbf(o00, o01);
                    *(uint32_t*)&rowp[d + 32] = pkbf(o10, o11);
                }
            }
        }
    }
}

// ---------------- O projection + gated residual + layer scale (BM=128, BN=64) ----------------
__global__ void __launch_bounds__(256, 2)
gemm_o(const bf16* __restrict__ A, float* __restrict__ out,
       const float* __restrict__ hid, const float* __restrict__ c3,
       const float* __restrict__ gate, const float* __restrict__ ls) {
    extern __shared__ char sm[];
    const int bm = blockIdx.y * 128, bn = blockIdx.x * 64;
    GemmCore<2, 4> core;
    core.run(A, g_wo, bm, bn, sm);

    const int tid = threadIdx.x, warp = tid >> 5, lane = tid & 31;
    const int g = lane >> 2, tg = lane & 3;
    const int wm = (warp >> 1) * 32, wn = (warp & 1) * 32;
    float gs[4][2], lv[4][2];
#pragma unroll
    for (int nt = 0; nt < 4; nt++) {
        int c = bn + wn + nt * 8 + tg * 2;
        float2 gv = *(const float2*)&gate[c];
        float2 l2 = *(const float2*)&ls[c];
        gs[nt][0] = 1.f / (1.f + __expf(-gv.x));
        gs[nt][1] = 1.f / (1.f + __expf(-gv.y));
        lv[nt][0] = l2.x; lv[nt][1] = l2.y;
    }
#pragma unroll
    for (int mt = 0; mt < 2; mt++) {
#pragma unroll
        for (int half = 0; half < 2; half++) {
            int r = bm + wm + mt * 16 + g + half * 8;
#pragma unroll
            for (int nt = 0; nt < 4; nt++) {
                int c = bn + wn + nt * 8 + tg * 2;
                size_t idx = (size_t)r * HH + c;
                float a0 = core.acc[mt][nt][half * 2], a1 = core.acc[mt][nt][half * 2 + 1];
                float2 hv = *(const float2*)&hid[idx];
                float2 cv = *(const float2*)&c3[idx];
                float2 ov;
                ov.x = hv.x + lv[nt][0] * (gs[nt][0] * a0 + (1.f - gs[nt][0]) * cv.x);
                ov.y = hv.y + lv[nt][1] * (gs[nt][1] * a1 + (1.f - gs[nt][1]) * cv.y);
                *(float2*)&out[idx] = ov;
            }
        }
    }
}

// ---------------- flash attention: BM=256, 16 warps, 6-stage ring (known-best R9 config) ----------------
#define FL_ST 9216                  /* 64 x 144 B per tensor per stage */
#define FL_SMEM (12 * FL_ST)        /* 110592: K stages [0..6), V stages [6..12) */
#define FL_TILES (LL / 64)          /* 80 */

__global__ void __launch_bounds__(512, 1) flash_attn() {
    extern __shared__ char sm[];
    const int b = blockIdx.z, h = blockIdx.y, q0 = blockIdx.x * 256;
    const bf16*   Qp = g_qh + ((size_t)(b * NHH + h)) * SS * HDD;
    const bf16*   Kp = g_kh + ((size_t)(b * NHH + h)) * LL * HDD;
    const __half* Vp = g_vh + ((size_t)(b * NHH + h)) * LL * HDD;
    const unsigned smK = smemu(sm);
    const unsigned smV = smK + 6 * FL_ST;
    const int tid = threadIdx.x, warp = tid >> 5, lane = tid & 31;
    const int g = lane >> 2, tg = lane & 3;
    const int kRow = (lane & 7) + ((lane & 16) ? 8 : 0);
    const int kCol = (lane & 8);
    const int vRow = lane & 15;
    const int vCol = (lane & 16) ? 8 : 0;
    const unsigned kAddr = smK + kRow * 144 + kCol * 2;
    const unsigned vAddr = smV + vRow * 144 + vCol * 2;

    uint32_t qf[4][4];
    {
        int r = q0 + warp * 16 + g;
#pragma unroll
        for (int kt = 0; kt < 4; kt++) {
            qf[kt][0] = *(const uint32_t*)&Qp[(size_t)r * HDD + kt * 16 + tg * 2];
            qf[kt][1] = *(const uint32_t*)&Qp[(size_t)(r + 8) * HDD + kt * 16 + tg * 2];
            qf[kt][2] = *(const uint32_t*)&Qp[(size_t)r * HDD + kt * 16 + 8 + tg * 2];
            qf[kt][3] = *(const uint32_t*)&Qp[(size_t)(r + 8) * HDD + kt * 16 + 8 + tg * 2];
        }
    }
    float l0 = 0.f, l1 = 0.f;
    float o[8][4];
#pragma unroll
    for (int nt = 0; nt < 8; nt++)
#pragma unroll
        for (int i = 0; i < 4; i++) o[nt][i] = 0.f;

    // 512 threads: one cpa16 per tensor per thread covers a 64-row stage
    auto load_kv = [&](int st, int j) {
        const bf16*   Kt = Kp + (size_t)j * 64 * HDD;
        const __half* Vt = Vp + (size_t)j * 64 * HDD;
        int r = tid >> 3, c = tid & 7;
        cpa16(smK + st * FL_ST + r * 144 + c * 16, Kt + (size_t)r * HDD + c * 8);
        cpa16(smV + st * FL_ST + r * 144 + c * 16, Vt + (size_t)r * HDD + c * 8);
        cpcommit();
    };

#pragma unroll
    for (int j = 0; j < 4; j++) load_kv(j, j);

    int s = 0;
    for (int j = 0; j < FL_TILES; j++) {
        if (j + 4 < FL_TILES) {
            load_kv((s + 4 >= 6) ? s - 2 : s + 4, j + 4);
            cpwait<4>();
        } else {
            if (j + 4 == FL_TILES)      { cpwait<3>(); }
            else if (j + 3 == FL_TILES) { cpwait<2>(); }
            else if (j + 2 == FL_TILES) { cpwait<1>(); }
            else                        { cpwait<0>(); }
        }
        __syncthreads();

        // S = Q K^T (bf16)
        float sacc[8][4];
#pragma unroll
        for (int nt = 0; nt < 8; nt++)
#pragma unroll
            for (int i = 0; i < 4; i++) sacc[nt][i] = 0.f;
        const unsigned kSt = kAddr + s * FL_ST;
#pragma unroll
        for (int kt = 0; kt < 4; kt++) {
            const int k0 = kt * 16;
#pragma unroll
            for (int np = 0; np < 4; np++) {
                uint32_t r0, r1, r2, r3;
                ldmA(r0, r1, r2, r3, kSt + np * 16 * 144 + k0 * 2);
                uint32_t b0[2] = { r0, r1 };
                uint32_t b1[2] = { r2, r3 };
                mma16816(sacc[np * 2], qf[kt], b0);
                mma16816(sacc[np * 2 + 1], qf[kt], b1);
            }
        }

        // P = exp2(S) in f16x2
        uint32_t pf[4][4];
#pragma unroll
        for (int nt = 0; nt < 8; nt++) {
            pf[nt >> 1][(nt & 1) * 2 + 0] = ex2h2(cvth2(sacc[nt][1], sacc[nt][0]));
            pf[nt >> 1][(nt & 1) * 2 + 1] = ex2h2(cvth2(sacc[nt][3], sacc[nt][2]));
        }
        // l accumulation via HADD2 tree
        {
            uint32_t s0 = hadd2(hadd2(hadd2(pf[0][0], pf[1][0]), hadd2(pf[2][0], pf[3][0])),
                                hadd2(hadd2(pf[0][2], pf[1][2]), hadd2(pf[2][2], pf[3][2])));
            uint32_t s1 = hadd2(hadd2(hadd2(pf[0][1], pf[1][1]), hadd2(pf[2][1], pf[3][1])),
                                hadd2(hadd2(pf[0][3], pf[1][3]), hadd2(pf[2][3], pf[3][3])));
            __half2 h0 = *reinterpret_cast<__half2*>(&s0);
            __half2 h1 = *reinterpret_cast<__half2*>(&s1);
            l0 += __low2float(h0) + __high2float(h0);
            l1 += __low2float(h1) + __high2float(h1);
        }

        // O += P V (f16)
        const unsigned vSt = vAddr + s * FL_ST;
#pragma unroll
        for (int kt = 0; kt < 4; kt++) {
            const int k0 = kt * 16;
#pragma unroll
            for (int np = 0; np < 4; np++) {
                uint32_t r0, r1, r2, r3;
                ldmT(r0, r1, r2, r3, vSt + k0 * 144 + np * 16 * 2);
                uint32_t b0[2] = { r0, r1 };
                uint32_t b1[2] = { r2, r3 };
                mma16816h(o[np * 2], pf[kt], b0);
                mma16816h(o[np * 2 + 1], pf[kt], b1);
            }
        }
        if (++s == 6) s = 0;
    }

    // final row-sum reduce
    l0 += __shfl_xor_sync(0xffffffffu, l0, 1);
    l0 += __shfl_xor_sync(0xffffffffu, l0, 2);
    l1 += __shfl_xor_sync(0xffffffffu, l1, 1);
    l1 += __shfl_xor_sync(0xffffffffu, l1, 2);

    float il0 = 1.f / l0, il1 = 1.f / l1;
    int r = b * SS + q0 + warp * 16 + g;
    bf16* cp  = g_ctx + (size_t)r * HH + h * HDD;
    bf16* cp8 = g_ctx + (size_t)(r + 8) * HH + h * HDD;
#pragma unroll
    for (int nt = 0; nt < 8; nt++) {
        int c = nt * 8 + tg * 2;
        *(uint32_t*)&cp[c]  = pkbf(o[nt][0] * il0, o[nt][1] * il0);
        *(uint32_t*)&cp8[c] = pkbf(o[nt][2] * il1, o[nt][3] * il1);
    }
}

// ---------------- launch ----------------
extern "C" void kernel_launch(void* const* d_in, const int* in_sizes, int n_in,
                              void* d_out, int out_size) {
    const float* hidden = (const float*)d_in[0];
    const float* cache  = (const float*)d_in[1];
    const float* ln_s   = (const float*)d_in[2];
    const float* ln_b   = (const float*)d_in[3];
    const float* Wq     = (const float*)d_in[4];
    const float* Wk     = (const float*)d_in[5];
    const float* Wv     = (const float*)d_in[6];
    const float* Wo     = (const float*)d_in[7];
    const float* gate   = (const float*)d_in[8];
    const float* ls     = (const float*)d_in[9];
    float* out = (float*)d_out;

    void* p_kv; void* p_ctx;
    cudaGetSymbolAddress(&p_kv, g_kv);
    cudaGetSymbolAddress(&p_ctx, g_ctx);

    cudaFuncSetAttribute(qkv_gemm,   cudaFuncAttributeMaxDynamicSharedMemorySize, GE_SMEM_QKV);
    cudaFuncSetAttribute(gemm_o,     cudaFuncAttributeMaxDynamicSharedMemorySize, GE_SMEM_O);
    cudaFuncSetAttribute(flash_attn, cudaFuncAttributeMaxDynamicSharedMemorySize, FL_SMEM);

    prologue<<<12416, 256>>>(Wq, Wk, Wv, Wo, cache, out, hidden, ln_s, ln_b);

    qkv_gemm<<<dim3(8, 88, BB), 256, GE_SMEM_QKV>>>((const bf16*)p_kv);

    flash_attn<<<dim3(SS / 256, NHH, BB), 512, FL_SMEM>>>();

    gemm_o<<<dim3(16, 16), 256, GE_SMEM_O>>>((const bf16*)p_ctx, out, hidden,
                                             cache + (size_t)3 * BB * SS * HH, gate, ls);

    ln_to_out<<<BB * SS, 256>>>(out, ln_s, ln_b, out + (size_t)WW * BB * SS * HH);
}